// round 2
// baseline (speedup 1.0000x reference)
#include <cuda_runtime.h>
#include <math.h>

#define NB 16
#define NT 8
#define LT 2048
#define NEP 920     // stored proj channels: 0..895 = xBC(x|B), 896..919 = dt_raw heads
#define WTS 960     // padded Wt row stride
#define NXS 896
#define NH 24
#define HD 32
#define DS 128
#define DM 192

__device__ float g_proj[(size_t)NB*LT*NEP];
__device__ float g_xs[(size_t)NB*LT*NXS];
__device__ float g_w[(size_t)NB*LT*NH];
__device__ float g_tail[(size_t)NB*NH*LT];
__device__ float g_Zsub[NB*8*4*4096];
__device__ float g_C[NB*8*4096];
__device__ float g_S[NB*8*4096];
__device__ float g_part[8*128*100];
__device__ float g_Wt[192*WTS];
__device__ float g_peproj[8*NEP];

__device__ __forceinline__ float softplus_f(float z){
    return log1pf(expf(-fabsf(z))) + fmaxf(z, 0.f);
}
__device__ __forceinline__ float silu_f(float v){
    return v / (1.f + expf(-v));
}
// stored channel -> in_proj_w row (skip unused "C" channels 896..1023 of xBC)
__device__ __forceinline__ int wrow_of(int ce){
    return (ce < 896) ? (768 + ce) : (896 + ce);   // ce>=896 maps to 1792+(ce-896)
}

// ---- transpose W (needed cols only) into [k][e] with zero pad to WTS ----
__global__ void k_wt(const float* __restrict__ in_proj_w){
    int i = blockIdx.x*blockDim.x + threadIdx.x;
    if (i >= 192*WTS) return;
    int k = i / WTS, e = i % WTS;
    g_Wt[i] = (e < NEP) ? in_proj_w[(size_t)wrow_of(e)*DM + k] : 0.f;
}

// ---- positional encoding rows projected through W (shared by all batches) ----
__global__ void k_peproj(const float* __restrict__ in_proj_w){
    __shared__ float pe[DM];
    int t = blockIdx.x;
    int tid = threadIdx.x;
    if (tid < DM){
        float expo = -(float)(tid & ~1) * (logf(10000.0f)/(float)DM);
        float div = expf(expo);
        float ang = (float)t * div;
        pe[tid] = (tid & 1) ? cosf(ang) : sinf(ang);
    }
    __syncthreads();
    for (int e = tid; e < NEP; e += blockDim.x){
        const float* wr = in_proj_w + (size_t)wrow_of(e)*DM;
        float s = 0.f;
        for (int d = 0; d < DM; d++) s += pe[d]*wr[d];
        g_peproj[t*NEP + e] = s;
    }
}

// ---- padded half of every chunk (s in 128..255) is exactly the PE projection ----
__global__ void k_fillpad(){
    size_t total = (size_t)NB*NT*128*NEP;
    for (size_t i = (size_t)blockIdx.x*blockDim.x + threadIdx.x; i < total;
         i += (size_t)gridDim.x*blockDim.x){
        int e = (int)(i % NEP); size_t r = i / NEP;
        int sp = (int)(r % 128); r /= 128;
        int t = (int)(r % NT); int b = (int)(r / NT);
        int l = t*256 + 128 + sp;
        g_proj[((size_t)b*LT + l)*NEP + e] = g_peproj[t*NEP + e];
    }
}

// ---- main GEMM: 16384 real rows x 920 cols x K=192, + peproj bias ----
__global__ __launch_bounds__(256) void k_gemm(const float* __restrict__ inputs){
    int rb = blockIdx.x;
    int b = rb >> 4;
    int t = (rb >> 1) & 7;
    int s0 = (rb & 1) * 64;
    int e0 = blockIdx.y * 64;
    const float* A = inputs + ((size_t)(b*8 + t)*129 + (size_t)(s0 + 1))*DM;
    __shared__ float As[16][64];
    __shared__ float Bs[16][64];
    int tid = threadIdx.x;
    int tx = tid & 15, ty = tid >> 4;
    int am = tid >> 2, akq = (tid & 3)*4;
    int bk = tid >> 4, bj = (tid & 15)*4;
    float acc[4][4] = {};
    for (int k0 = 0; k0 < DM; k0 += 16){
        float4 av = *reinterpret_cast<const float4*>(A + (size_t)am*DM + k0 + akq);
        float4 bv = *reinterpret_cast<const float4*>(&g_Wt[(size_t)(k0 + bk)*WTS + e0 + bj]);
        __syncthreads();
        As[akq+0][am] = av.x; As[akq+1][am] = av.y; As[akq+2][am] = av.z; As[akq+3][am] = av.w;
        *reinterpret_cast<float4*>(&Bs[bk][bj]) = bv;
        __syncthreads();
        #pragma unroll
        for (int k = 0; k < 16; k++){
            float4 a  = *reinterpret_cast<const float4*>(&As[k][ty*4]);
            float4 bb = *reinterpret_cast<const float4*>(&Bs[k][tx*4]);
            float ar[4] = {a.x, a.y, a.z, a.w};
            float br[4] = {bb.x, bb.y, bb.z, bb.w};
            #pragma unroll
            for (int i = 0; i < 4; i++)
                #pragma unroll
                for (int j = 0; j < 4; j++)
                    acc[i][j] += ar[i]*br[j];
        }
    }
    #pragma unroll
    for (int i = 0; i < 4; i++){
        int s = s0 + ty*4 + i;
        int l = t*256 + s;
        float* dst = g_proj + ((size_t)b*LT + l)*NEP;
        #pragma unroll
        for (int j = 0; j < 4; j++){
            int e = e0 + tx*4 + j;
            if (e < NEP) dst[e] = acc[i][j] + g_peproj[t*NEP + e];
        }
    }
}

// ---- depthwise causal conv(4) + silu over the full 2048 sequence ----
__global__ __launch_bounds__(128) void k_conv(const float* __restrict__ conv_w,
                                              const float* __restrict__ conv_b){
    int b = blockIdx.x >> 7;
    int l0 = (blockIdx.x & 127) * 16;
    int c = blockIdx.y * 128 + threadIdx.x;     // c < 896
    __shared__ float sm[19][128];
    for (int r = 0; r < 19; r++){
        int gl = l0 + r - 3;
        sm[r][threadIdx.x] = (gl >= 0) ? g_proj[((size_t)b*LT + gl)*NEP + c] : 0.f;
    }
    __syncthreads();
    float4 wv = *reinterpret_cast<const float4*>(conv_w + (size_t)c*4);
    float cb = conv_b[c];
    #pragma unroll
    for (int j = 0; j < 16; j++){
        float v = cb + sm[j][threadIdx.x]*wv.x + sm[j+1][threadIdx.x]*wv.y
                     + sm[j+2][threadIdx.x]*wv.z + sm[j+3][threadIdx.x]*wv.w;
        g_xs[((size_t)b*LT + l0 + j)*NXS + c] = silu_f(v);
    }
}

// ---- per-(b,h): dt, logdA, reverse-exclusive cumsum (fp64), w = dt*exp(tail) ----
__global__ __launch_bounds__(128) void k_scan(const float* __restrict__ dt_bias,
                                              const float* __restrict__ A_log){
    int b = blockIdx.x / NH, h = blockIdx.x % NH;
    int tid = threadIdx.x;
    float db = dt_bias[h];
    float nA = expf(A_log[h]);
    float dtv[16], ldv[16];
    double cs = 0.0;
    #pragma unroll
    for (int j = 0; j < 16; j++){
        int l = tid*16 + j;
        float z = g_proj[((size_t)b*LT + l)*NEP + 896 + h] + db;
        float dt = softplus_f(z);
        dtv[j] = dt;
        float ld = -nA*dt;
        ldv[j] = ld;
        cs += (double)ld;
    }
    __shared__ double ch[128];
    ch[tid] = cs;
    __syncthreads();
    if (tid == 0){
        double acc = 0.0;
        for (int i = 127; i >= 0; i--){ double v = ch[i]; ch[i] = acc; acc += v; }
    }
    __syncthreads();
    double acc = ch[tid];
    for (int j = 15; j >= 0; j--){
        int l = tid*16 + j;
        float tl = (float)acc;
        g_w[((size_t)b*LT + l)*NH + h] = dtv[j]*expf(tl);
        g_tail[((size_t)(b*NH + h))*LT + l] = tl;
        acc += (double)ldv[j];
    }
}

// ---- segment outer products: Z[b][seg][sub][p][n] over l-ranges [256t+3, 256(t+1)+3) ----
__global__ __launch_bounds__(128) void k_seg(){
    int idx = blockIdx.x;
    int b = idx >> 5, seg = (idx >> 2) & 7, sub = idx & 3;
    int lbeg = seg*256 + 3 + sub*64;
    int lend = min(seg*256 + 3 + (sub + 1)*64, LT);
    int n = threadIdx.x;
    __shared__ float wsh[NH];
    __shared__ float ysh[HD];
    float acc[HD];
    #pragma unroll
    for (int p = 0; p < HD; p++) acc[p] = 0.f;
    for (int l = lbeg; l < lend; l++){
        size_t base = (size_t)b*LT + l;
        if (n < NH) wsh[n] = g_w[base*NH + n];
        float Bn = g_xs[base*NXS + 768 + n];
        __syncthreads();
        if (n < HD){
            const float* xp = g_xs + base*NXS + n;
            float y = 0.f;
            #pragma unroll
            for (int h = 0; h < NH; h++) y += wsh[h]*xp[h*HD];
            ysh[n] = y;
        }
        __syncthreads();
        #pragma unroll
        for (int p = 0; p < HD; p++) acc[p] += ysh[p]*Bn;
    }
    float* Z = g_Zsub + (size_t)idx*4096;
    #pragma unroll
    for (int p = 0; p < HD; p++) Z[p*DS + n] = acc[p];
}

// ---- per-(b,t) 3-position boundary correction (truncated conv of each suffix) ----
__global__ __launch_bounds__(128) void k_bdry(const float* __restrict__ conv_w,
                                              const float* __restrict__ conv_b,
                                              const float* __restrict__ dt_bias,
                                              const float* __restrict__ A_log){
    int b = blockIdx.x >> 3, t = blockIdx.x & 7;
    int l0 = t*256;
    int tid = threadIdx.x;
    __shared__ float xsb[3][NXS];
    __shared__ float dtb[3][NH], ldb[3][NH], wjs[3][NH];
    __shared__ float ysh[3][HD];
    for (int c = tid; c < NXS; c += 128){
        float4 wv = *reinterpret_cast<const float4*>(conv_w + (size_t)c*4);
        float w[4] = {wv.x, wv.y, wv.z, wv.w};
        float cb = conv_b[c];
        #pragma unroll
        for (int j = 0; j < 3; j++){
            float v = cb;
            for (int k = 3-j; k <= 3; k++)
                v += g_proj[((size_t)b*LT + (l0 + j - 3 + k))*NEP + c]*w[k];
            xsb[j][c] = silu_f(v);
        }
    }
    if (tid < NH){
        int h = tid;
        float db = dt_bias[h], nA = expf(A_log[h]);
        for (int j = 0; j < 3; j++){
            float z = g_proj[((size_t)b*LT + l0 + j)*NEP + 896 + h] + db;
            float dt = softplus_f(z);
            dtb[j][h] = dt; ldb[j][h] = -nA*dt;
        }
    }
    __syncthreads();
    if (tid < NH){
        int h = tid;
        float t2 = g_tail[((size_t)(b*NH + h))*LT + (l0 + 2)];
        wjs[2][h] = dtb[2][h]*expf(t2);
        float t1 = t2 + ldb[2][h];
        wjs[1][h] = dtb[1][h]*expf(t1);
        float t0 = t1 + ldb[1][h];
        wjs[0][h] = dtb[0][h]*expf(t0);
    }
    __syncthreads();
    if (tid < 96){
        int j = tid >> 5, p = tid & 31;
        float y = 0.f;
        #pragma unroll
        for (int h = 0; h < NH; h++) y += wjs[j][h]*xsb[j][h*HD + p];
        ysh[j][p] = y;
    }
    __syncthreads();
    int n = tid;
    float B0 = xsb[0][768+n], B1 = xsb[1][768+n], B2 = xsb[2][768+n];
    float* C = g_C + (size_t)blockIdx.x*4096;
    #pragma unroll
    for (int p = 0; p < HD; p++)
        C[p*DS + n] = ysh[0][p]*B0 + ysh[1][p]*B1 + ysh[2][p]*B2;
}

// ---- suffix-sum segments + add boundary corrections ----
__global__ void k_finalS(){
    int b = blockIdx.x;
    for (int i = threadIdx.x; i < 4096; i += blockDim.x){
        float run = 0.f;
        for (int t = 7; t >= 0; t--){
            size_t zb = ((size_t)(b*8 + t))*4*4096 + i;
            run += g_Zsub[zb] + g_Zsub[zb + 4096] + g_Zsub[zb + 2*4096] + g_Zsub[zb + 3*4096];
            g_S[(size_t)(b*8 + t)*4096 + i] = run + g_C[(size_t)(b*8 + t)*4096 + i];
        }
    }
}

// ---- classifier GEMM, split-K into deterministic partials ----
__global__ __launch_bounds__(256) void k_cls(const float* __restrict__ cls_w){
    int m0 = blockIdx.x*32, n0 = blockIdx.y*32;
    int kz0 = blockIdx.z*512;
    __shared__ float As[32][33], Bs[32][33];
    int tid = threadIdx.x;
    int tx = tid & 15, ty = tid >> 4;
    int am = tid >> 3, aq = (tid & 7)*4;
    float acc00 = 0, acc01 = 0, acc10 = 0, acc11 = 0;
    bool bvalid = (n0 + am) < 100;
    for (int k0 = kz0; k0 < kz0 + 512; k0 += 32){
        float4 av = *reinterpret_cast<const float4*>(g_S + (size_t)(m0 + am)*4096 + k0 + aq);
        float4 bv = bvalid ? *reinterpret_cast<const float4*>(cls_w + (size_t)(n0 + am)*4096 + k0 + aq)
                           : make_float4(0.f, 0.f, 0.f, 0.f);
        __syncthreads();
        As[am][aq+0] = av.x; As[am][aq+1] = av.y; As[am][aq+2] = av.z; As[am][aq+3] = av.w;
        Bs[aq+0][am] = bv.x; Bs[aq+1][am] = bv.y; Bs[aq+2][am] = bv.z; Bs[aq+3][am] = bv.w;
        __syncthreads();
        #pragma unroll
        for (int k = 0; k < 32; k++){
            float a0 = As[ty*2][k],   a1 = As[ty*2+1][k];
            float b0 = Bs[k][tx*2],   b1 = Bs[k][tx*2+1];
            acc00 += a0*b0; acc01 += a0*b1; acc10 += a1*b0; acc11 += a1*b1;
        }
    }
    int m = m0 + ty*2, n = n0 + tx*2;
    float* P = g_part + (size_t)blockIdx.z*12800;
    if (n < 100)    { P[m*100 + n]     = acc00; P[(m+1)*100 + n]     = acc10; }
    if (n + 1 < 100){ P[m*100 + n + 1] = acc01; P[(m+1)*100 + n + 1] = acc11; }
}

__global__ void k_out(const float* __restrict__ cls_b, float* __restrict__ out){
    int i = blockIdx.x*blockDim.x + threadIdx.x;
    if (i >= 12800) return;
    int k = i % 100;
    float s = cls_b[k];
    #pragma unroll
    for (int z = 0; z < 8; z++) s += g_part[z*12800 + i];
    out[i] = s;
}

extern "C" void kernel_launch(void* const* d_in, const int* in_sizes, int n_in,
                              void* d_out, int out_size){
    const float* inputs    = (const float*)d_in[0];
    const float* in_proj_w = (const float*)d_in[1];
    const float* conv_w    = (const float*)d_in[2];
    const float* conv_b    = (const float*)d_in[3];
    const float* dt_bias   = (const float*)d_in[4];
    const float* A_log     = (const float*)d_in[5];
    const float* cls_w     = (const float*)d_in[6];
    const float* cls_b     = (const float*)d_in[7];
    float* out = (float*)d_out;

    k_wt<<<720, 256>>>(in_proj_w);
    k_peproj<<<8, 256>>>(in_proj_w);
    k_fillpad<<<4096, 256>>>();
    k_gemm<<<dim3(256, 15), 256>>>(inputs);
    k_conv<<<dim3(16*128, 7), 128>>>(conv_w, conv_b);
    k_scan<<<16*24, 128>>>(dt_bias, A_log);
    k_seg<<<512, 128>>>();
    k_bdry<<<128, 128>>>(conv_w, conv_b, dt_bias, A_log);
    k_finalS<<<16, 256>>>();
    k_cls<<<dim3(4, 4, 8), 256>>>(cls_w);
    k_out<<<50, 256>>>(cls_b, out);
}

// round 4
// speedup vs baseline: 1.2572x; 1.2572x over previous
#include <cuda_runtime.h>
#include <math.h>

#define NB 16
#define NT 8
#define LT 2048
#define NEP 920     // stored proj channels: 0..895 = xBC(x|B), 896..919 = dt_raw heads
#define WTS 1024    // padded Wt row stride
#define NH 24
#define HD 32
#define DS 128
#define DM 192

// proj of REAL rows only: [b][t][128][NEP]
__device__ float g_projR[(size_t)NB*NT*128*NEP];
__device__ float g_y[(size_t)NB*LT*HD];
__device__ float g_B[(size_t)NB*LT*DS];
__device__ float g_w[(size_t)NB*LT*NH];
__device__ float g_tail[(size_t)NB*NH*LT];
__device__ float g_Zsub[NB*8*4*4096];
__device__ float g_C[NB*8*4096];
__device__ float g_S[NB*8*4096];
__device__ float g_part[8*128*100];
__device__ float g_Wt[192*WTS];
__device__ float g_peproj[8*NEP];

__device__ __forceinline__ float softplus_f(float z){
    return log1pf(expf(-fabsf(z))) + fmaxf(z, 0.f);
}
__device__ __forceinline__ float silu_f(float v){
    return v / (1.f + expf(-v));
}
// stored channel -> in_proj_w row (skip unused "C" channels 896..1023 of xBC)
__device__ __forceinline__ int wrow_of(int ce){
    return (ce < 896) ? (768 + ce) : (896 + ce);
}
// proj value at (b, l, e): pad rows (l%256 >= 128) are the PE projection
__device__ __forceinline__ float ld_proj(int b, int l, int e){
    int r = l & 255;
    if (r >= 128) return g_peproj[(l >> 8)*NEP + e];
    return g_projR[(((size_t)b*NT + (l >> 8))*128 + r)*NEP + e];
}

// ---- transpose W (needed cols only) into [k][e] with zero pad to WTS ----
__global__ void k_wt(const float* __restrict__ in_proj_w){
    int i = blockIdx.x*blockDim.x + threadIdx.x;
    if (i >= 192*WTS) return;
    int k = i / WTS, e = i % WTS;
    g_Wt[i] = (e < NEP) ? in_proj_w[(size_t)wrow_of(e)*DM + k] : 0.f;
}

// ---- positional encoding rows projected through W (shared by all batches) ----
__global__ void k_peproj(const float* __restrict__ in_proj_w){
    __shared__ float pe[DM];
    int t = blockIdx.x;
    int tid = threadIdx.x;
    if (tid < DM){
        float expo = -(float)(tid & ~1) * (logf(10000.0f)/(float)DM);
        float div = expf(expo);
        float ang = (float)t * div;
        pe[tid] = (tid & 1) ? cosf(ang) : sinf(ang);
    }
    __syncthreads();
    for (int e = tid; e < NEP; e += blockDim.x){
        const float* wr = in_proj_w + (size_t)wrow_of(e)*DM;
        float s = 0.f;
        for (int d = 0; d < DM; d++) s += pe[d]*wr[d];
        g_peproj[t*NEP + e] = s;
    }
}

// ---- main GEMM: 16384 real rows x 920(->1024) cols x K=192, + peproj bias ----
// 128x128 tile, 8x8 per thread (split 4+64 cols/rows), double-buffered smem.
__global__ void __launch_bounds__(256, 2) k_gemm(const float* __restrict__ inputs){
    int bt = blockIdx.x;                 // b*8+t, 0..127; block covers its 128 real rows
    int t = bt & 7;
    int e0 = blockIdx.y * 128;
    const float* A = inputs + ((size_t)bt*129 + 1)*DM;   // [128][192]
    __shared__ float As[2][16][128];
    __shared__ float Bs[2][16][128];
    int tid = threadIdx.x;
    int am = tid & 127, kq = (tid >> 7) * 8;     // A ldg: row am, k kq..kq+7
    int bk = tid >> 5,  bj = (tid & 31) * 4;     // B ldg: rows bk,bk+8, col bj
    int ty = tid >> 4,  tx = tid & 15;
    float acc[8][8];
    #pragma unroll
    for (int i = 0; i < 8; i++)
        #pragma unroll
        for (int j = 0; j < 8; j++) acc[i][j] = 0.f;

    float4 ra0, ra1, rb0, rb1;
    ra0 = *(const float4*)(A + (size_t)am*DM + kq);
    ra1 = *(const float4*)(A + (size_t)am*DM + kq + 4);
    rb0 = *(const float4*)(g_Wt + (size_t)bk*WTS + e0 + bj);
    rb1 = *(const float4*)(g_Wt + (size_t)(bk + 8)*WTS + e0 + bj);
    As[0][kq+0][am] = ra0.x; As[0][kq+1][am] = ra0.y; As[0][kq+2][am] = ra0.z; As[0][kq+3][am] = ra0.w;
    As[0][kq+4][am] = ra1.x; As[0][kq+5][am] = ra1.y; As[0][kq+6][am] = ra1.z; As[0][kq+7][am] = ra1.w;
    *(float4*)&Bs[0][bk][bj]     = rb0;
    *(float4*)&Bs[0][bk+8][bj]   = rb1;
    __syncthreads();

    #pragma unroll 1
    for (int kb = 0; kb < 12; kb++){
        int cur = kb & 1;
        if (kb < 11){
            int k0 = (kb + 1) * 16;
            ra0 = *(const float4*)(A + (size_t)am*DM + k0 + kq);
            ra1 = *(const float4*)(A + (size_t)am*DM + k0 + kq + 4);
            rb0 = *(const float4*)(g_Wt + (size_t)(k0 + bk)*WTS + e0 + bj);
            rb1 = *(const float4*)(g_Wt + (size_t)(k0 + bk + 8)*WTS + e0 + bj);
        }
        #pragma unroll
        for (int k = 0; k < 16; k++){
            float4 av0 = *(const float4*)&As[cur][k][ty*4];
            float4 av1 = *(const float4*)&As[cur][k][ty*4 + 64];
            float4 bv0 = *(const float4*)&Bs[cur][k][tx*4];
            float4 bv1 = *(const float4*)&Bs[cur][k][tx*4 + 64];
            float ar[8] = {av0.x, av0.y, av0.z, av0.w, av1.x, av1.y, av1.z, av1.w};
            float br[8] = {bv0.x, bv0.y, bv0.z, bv0.w, bv1.x, bv1.y, bv1.z, bv1.w};
            #pragma unroll
            for (int i = 0; i < 8; i++)
                #pragma unroll
                for (int j = 0; j < 8; j++)
                    acc[i][j] += ar[i]*br[j];
        }
        if (kb < 11){
            int nxt = cur ^ 1;
            As[nxt][kq+0][am] = ra0.x; As[nxt][kq+1][am] = ra0.y;
            As[nxt][kq+2][am] = ra0.z; As[nxt][kq+3][am] = ra0.w;
            As[nxt][kq+4][am] = ra1.x; As[nxt][kq+5][am] = ra1.y;
            As[nxt][kq+6][am] = ra1.z; As[nxt][kq+7][am] = ra1.w;
            *(float4*)&Bs[nxt][bk][bj]   = rb0;
            *(float4*)&Bs[nxt][bk+8][bj] = rb1;
            __syncthreads();
        }
    }

    // epilogue: add PE projection, store real rows
    float bias[8];
    #pragma unroll
    for (int j = 0; j < 8; j++){
        int e = e0 + tx*4 + (j >> 2)*64 + (j & 3);
        bias[j] = (e < NEP) ? g_peproj[t*NEP + e] : 0.f;
    }
    #pragma unroll
    for (int i = 0; i < 8; i++){
        int s = ty*4 + (i >> 2)*64 + (i & 3);
        float* dst = g_projR + ((size_t)bt*128 + s)*NEP;
        int eA = e0 + tx*4;
        if (eA < NEP){
            float4 v = make_float4(acc[i][0]+bias[0], acc[i][1]+bias[1],
                                   acc[i][2]+bias[2], acc[i][3]+bias[3]);
            *(float4*)(dst + eA) = v;
        }
        int eB = e0 + tx*4 + 64;
        if (eB < NEP){
            float4 v = make_float4(acc[i][4]+bias[4], acc[i][5]+bias[5],
                                   acc[i][6]+bias[6], acc[i][7]+bias[7]);
            *(float4*)(dst + eB) = v;
        }
    }
}

// ---- per-(b,h): dt, logdA, reverse-exclusive cumsum (fp64), w = dt*exp(tail) ----
__global__ void __launch_bounds__(128) k_scan(const float* __restrict__ dt_bias,
                                              const float* __restrict__ A_log){
    int b = blockIdx.x / NH, h = blockIdx.x % NH;
    int tid = threadIdx.x;
    float db = dt_bias[h];
    float nA = expf(A_log[h]);
    float dtv[16], ldv[16];
    double cs = 0.0;
    #pragma unroll
    for (int j = 0; j < 16; j++){
        int l = tid*16 + j;
        float z = ld_proj(b, l, 896 + h) + db;
        float dt = softplus_f(z);
        dtv[j] = dt;
        float ld = -nA*dt;
        ldv[j] = ld;
        cs += (double)ld;
    }
    __shared__ double ch[128];
    ch[tid] = cs;
    __syncthreads();
    if (tid == 0){
        double acc = 0.0;
        for (int i = 127; i >= 0; i--){ double v = ch[i]; ch[i] = acc; acc += v; }
    }
    __syncthreads();
    double acc = ch[tid];
    for (int j = 15; j >= 0; j--){
        int l = tid*16 + j;
        float tl = (float)acc;
        g_w[((size_t)b*LT + l)*NH + h] = dtv[j]*expf(tl);
        g_tail[((size_t)(b*NH + h))*LT + l] = tl;
        acc += (double)ldv[j];
    }
}

// ---- fused conv(4)+silu over full 2048 seq, head-combine into y[l][32], B[l][128] ----
__global__ void __launch_bounds__(256) k_convy(const float* __restrict__ conv_w,
                                               const float* __restrict__ conv_b){
    int b = blockIdx.x >> 8;
    int l0 = (blockIdx.x & 255) * 8;
    int tid = threadIdx.x;
    __shared__ float pt[11][896];       // proj rows l0-3 .. l0+7
    __shared__ float wsm[8][NH];
    __shared__ float ypart[256][8];
    for (int i = tid; i < 11*896; i += 256){
        int r = i / 896, c = i - r*896;
        int gl = l0 - 3 + r;
        pt[r][c] = (gl >= 0) ? ld_proj(b, gl, c) : 0.f;
    }
    if (tid < 8*NH){
        int l = tid / NH, h = tid - (tid/NH)*NH;
        wsm[l][h] = g_w[((size_t)b*LT + l0 + l)*NH + h];
    }
    int c0 = tid, c1 = tid + 256, c2 = tid + 512;
    float4 w0 = *(const float4*)(conv_w + (size_t)c0*4);
    float4 w1 = *(const float4*)(conv_w + (size_t)c1*4);
    float4 w2 = *(const float4*)(conv_w + (size_t)c2*4);
    float cb0 = conv_b[c0], cb1 = conv_b[c1], cb2 = conv_b[c2];
    float4 wB = make_float4(0.f,0.f,0.f,0.f); float cbB = 0.f;
    if (tid < 128){ wB = *(const float4*)(conv_w + (size_t)(768 + tid)*4); cbB = conv_b[768 + tid]; }
    int h0 = tid >> 5;
    __syncthreads();
    float yl[8];
    #pragma unroll
    for (int j = 0; j < 8; j++){
        float v0 = cb0 + pt[j][c0]*w0.x + pt[j+1][c0]*w0.y + pt[j+2][c0]*w0.z + pt[j+3][c0]*w0.w;
        float v1 = cb1 + pt[j][c1]*w1.x + pt[j+1][c1]*w1.y + pt[j+2][c1]*w1.z + pt[j+3][c1]*w1.w;
        float v2 = cb2 + pt[j][c2]*w2.x + pt[j+1][c2]*w2.y + pt[j+2][c2]*w2.z + pt[j+3][c2]*w2.w;
        yl[j] = silu_f(v0)*wsm[j][h0] + silu_f(v1)*wsm[j][h0+8] + silu_f(v2)*wsm[j][h0+16];
        if (tid < 128){
            int cB = 768 + tid;
            float vB = cbB + pt[j][cB]*wB.x + pt[j+1][cB]*wB.y + pt[j+2][cB]*wB.z + pt[j+3][cB]*wB.w;
            g_B[((size_t)b*LT + l0 + j)*DS + tid] = silu_f(vB);
        }
    }
    #pragma unroll
    for (int j = 0; j < 8; j++) ypart[tid][j] = yl[j];
    __syncthreads();
    {
        int l = tid >> 5, p = tid & 31;
        float y = 0.f;
        #pragma unroll
        for (int g = 0; g < 8; g++) y += ypart[g*32 + p][l];
        g_y[((size_t)b*LT + l0 + l)*HD + p] = y;
    }
}

// ---- segment outer products: Z[p][n] = sum_l y[l,p]*B[l,n] over 64-l subsegments ----
__global__ void __launch_bounds__(128) k_seg(){
    int idx = blockIdx.x;
    int b = idx >> 5, seg = (idx >> 2) & 7, sub = idx & 3;
    int lbeg = seg*256 + 3 + sub*64;
    int lend = min(lbeg + 64, LT);
    int n = threadIdx.x;
    __shared__ float ysm[8][HD];
    float acc[HD];
    #pragma unroll
    for (int p = 0; p < HD; p++) acc[p] = 0.f;
    for (int l8 = lbeg; l8 < lend; l8 += 8){
        int cnt = min(8, lend - l8);
        __syncthreads();
        for (int i = n; i < cnt*HD; i += 128)
            ysm[i >> 5][i & 31] = g_y[((size_t)b*LT + l8 + (i >> 5))*HD + (i & 31)];
        __syncthreads();
        for (int j = 0; j < cnt; j++){
            float Bn = g_B[((size_t)b*LT + l8 + j)*DS + n];
            #pragma unroll
            for (int p = 0; p < HD; p++) acc[p] += ysm[j][p]*Bn;
        }
    }
    float* Z = g_Zsub + (size_t)idx*4096;
    #pragma unroll
    for (int p = 0; p < HD; p++) Z[p*DS + n] = acc[p];
}

// ---- per-(b,t) 3-position boundary correction (truncated conv of each suffix) ----
__global__ void __launch_bounds__(128) k_bdry(const float* __restrict__ conv_w,
                                              const float* __restrict__ conv_b,
                                              const float* __restrict__ dt_bias,
                                              const float* __restrict__ A_log){
    int b = blockIdx.x >> 3, t = blockIdx.x & 7;
    int l0 = t*256;
    int tid = threadIdx.x;
    __shared__ float xsb[3][896];
    __shared__ float dtb[3][NH], ldb[3][NH], wjs[3][NH];
    __shared__ float ysh[3][HD];
    for (int c = tid; c < 896; c += 128){
        float4 wv = *(const float4*)(conv_w + (size_t)c*4);
        float w[4] = {wv.x, wv.y, wv.z, wv.w};
        float cb = conv_b[c];
        #pragma unroll
        for (int j = 0; j < 3; j++){
            float v = cb;
            for (int k = 3-j; k <= 3; k++)
                v += g_projR[(((size_t)(b*NT + t))*128 + (j - 3 + k))*NEP + c]*w[k];
            xsb[j][c] = silu_f(v);
        }
    }
    if (tid < NH){
        int h = tid;
        float db = dt_bias[h], nA = expf(A_log[h]);
        for (int j = 0; j < 3; j++){
            float z = g_projR[(((size_t)(b*NT + t))*128 + j)*NEP + 896 + h] + db;
            float dt = softplus_f(z);
            dtb[j][h] = dt; ldb[j][h] = -nA*dt;
        }
    }
    __syncthreads();
    if (tid < NH){
        int h = tid;
        float t2 = g_tail[((size_t)(b*NH + h))*LT + (l0 + 2)];
        wjs[2][h] = dtb[2][h]*expf(t2);
        float t1 = t2 + ldb[2][h];
        wjs[1][h] = dtb[1][h]*expf(t1);
        float t0 = t1 + ldb[1][h];
        wjs[0][h] = dtb[0][h]*expf(t0);
    }
    __syncthreads();
    if (tid < 96){
        int j = tid >> 5, p = tid & 31;
        float y = 0.f;
        #pragma unroll
        for (int h = 0; h < NH; h++) y += wjs[j][h]*xsb[j][h*HD + p];
        ysh[j][p] = y;
    }
    __syncthreads();
    int n = tid;
    float B0 = xsb[0][768+n], B1 = xsb[1][768+n], B2 = xsb[2][768+n];
    float* C = g_C + (size_t)blockIdx.x*4096;
    #pragma unroll
    for (int p = 0; p < HD; p++)
        C[p*DS + n] = ysh[0][p]*B0 + ysh[1][p]*B1 + ysh[2][p]*B2;
}

// ---- suffix-sum segments + add boundary corrections ----
__global__ void k_finalS(){
    int b = blockIdx.x;
    for (int i = threadIdx.x; i < 4096; i += blockDim.x){
        float run = 0.f;
        for (int t = 7; t >= 0; t--){
            size_t zb = ((size_t)(b*8 + t))*4*4096 + i;
            run += g_Zsub[zb] + g_Zsub[zb + 4096] + g_Zsub[zb + 2*4096] + g_Zsub[zb + 3*4096];
            g_S[(size_t)(b*8 + t)*4096 + i] = run + g_C[(size_t)(b*8 + t)*4096 + i];
        }
    }
}

// ---- classifier GEMM, split-K into deterministic partials ----
__global__ void __launch_bounds__(256) k_cls(const float* __restrict__ cls_w){
    int m0 = blockIdx.x*32, n0 = blockIdx.y*32;
    int kz0 = blockIdx.z*512;
    __shared__ float As[32][33], Bs[32][33];
    int tid = threadIdx.x;
    int tx = tid & 15, ty = tid >> 4;
    int am = tid >> 3, aq = (tid & 7)*4;
    float acc00 = 0, acc01 = 0, acc10 = 0, acc11 = 0;
    bool bvalid = (n0 + am) < 100;
    for (int k0 = kz0; k0 < kz0 + 512; k0 += 32){
        float4 av = *reinterpret_cast<const float4*>(g_S + (size_t)(m0 + am)*4096 + k0 + aq);
        float4 bv = bvalid ? *reinterpret_cast<const float4*>(cls_w + (size_t)(n0 + am)*4096 + k0 + aq)
                           : make_float4(0.f, 0.f, 0.f, 0.f);
        __syncthreads();
        As[am][aq+0] = av.x; As[am][aq+1] = av.y; As[am][aq+2] = av.z; As[am][aq+3] = av.w;
        Bs[aq+0][am] = bv.x; Bs[aq+1][am] = bv.y; Bs[aq+2][am] = bv.z; Bs[aq+3][am] = bv.w;
        __syncthreads();
        #pragma unroll
        for (int k = 0; k < 32; k++){
            float a0 = As[ty*2][k],   a1 = As[ty*2+1][k];
            float b0 = Bs[k][tx*2],   b1 = Bs[k][tx*2+1];
            acc00 += a0*b0; acc01 += a0*b1; acc10 += a1*b0; acc11 += a1*b1;
        }
    }
    int m = m0 + ty*2, n = n0 + tx*2;
    float* P = g_part + (size_t)blockIdx.z*12800;
    if (n < 100)    { P[m*100 + n]     = acc00; P[(m+1)*100 + n]     = acc10; }
    if (n + 1 < 100){ P[m*100 + n + 1] = acc01; P[(m+1)*100 + n + 1] = acc11; }
}

__global__ void k_out(const float* __restrict__ cls_b, float* __restrict__ out){
    int i = blockIdx.x*blockDim.x + threadIdx.x;
    if (i >= 12800) return;
    int k = i % 100;
    float s = cls_b[k];
    #pragma unroll
    for (int z = 0; z < 8; z++) s += g_part[z*12800 + i];
    out[i] = s;
}

extern "C" void kernel_launch(void* const* d_in, const int* in_sizes, int n_in,
                              void* d_out, int out_size){
    const float* inputs    = (const float*)d_in[0];
    const float* in_proj_w = (const float*)d_in[1];
    const float* conv_w    = (const float*)d_in[2];
    const float* conv_b    = (const float*)d_in[3];
    const float* dt_bias   = (const float*)d_in[4];
    const float* A_log     = (const float*)d_in[5];
    const float* cls_w     = (const float*)d_in[6];
    const float* cls_b     = (const float*)d_in[7];
    float* out = (float*)d_out;

    k_wt<<<768, 256>>>(in_proj_w);
    k_peproj<<<8, 256>>>(in_proj_w);
    k_gemm<<<dim3(128, 8), 256>>>(inputs);
    k_scan<<<16*24, 128>>>(dt_bias, A_log);
    k_convy<<<16*256, 256>>>(conv_w, conv_b);
    k_seg<<<512, 128>>>();
    k_bdry<<<128, 128>>>(conv_w, conv_b, dt_bias, A_log);
    k_finalS<<<16, 256>>>();
    k_cls<<<dim3(4, 4, 8), 256>>>(cls_w);
    k_out<<<50, 256>>>(cls_b, out);
}

// round 6
// speedup vs baseline: 1.5698x; 1.2486x over previous
#include <cuda_runtime.h>
#include <math.h>

#define NB 16
#define NT 8
#define LT 2048
#define NEP 920     // stored proj channels: 0..895 = xBC(x|B), 896..919 = dt_raw heads
#define WTS 1024    // padded Wt row stride
#define NH 24
#define HD 32
#define DS 128
#define DM 192

// proj of REAL rows only: [b][t][128][NEP]
__device__ float g_projR[(size_t)NB*NT*128*NEP];
__device__ float g_y[(size_t)NB*LT*HD];
__device__ float g_B[(size_t)NB*LT*DS];
__device__ float g_w[(size_t)NB*NH*LT];          // [b][h][l]
__device__ float g_tail2[NB*NH*NT];              // tail at l0+2 per (b,h,t)
__device__ float g_wsum[NB*NT*NH];               // pad-region w sums
__device__ float g_Zsub[NB*8*2*4096];
__device__ float g_C[NB*8*4096];
__device__ float g_S[NB*8*4096];
__device__ float g_part[8*128*100];
__device__ float g_Wt[192*WTS];
__device__ float g_peproj[8*NEP];
__device__ float g_xc[8*896];                    // const-pad conv+silu per t
__device__ float g_dtpad[8*NH];
__device__ float g_ldpad[8*NH];

__device__ __forceinline__ float softplus_f(float z){
    return log1pf(expf(-fabsf(z))) + fmaxf(z, 0.f);
}
__device__ __forceinline__ float silu_f(float v){
    return v / (1.f + expf(-v));
}
__device__ __forceinline__ int wrow_of(int ce){
    return (ce < 896) ? (768 + ce) : (896 + ce);
}
// proj value at (b, l, e): pad rows (l%256 >= 128) are the PE projection
__device__ __forceinline__ float ld_proj(int b, int l, int e){
    int r = l & 255;
    if (r >= 128) return g_peproj[(l >> 8)*NEP + e];
    return g_projR[(((size_t)b*NT + (l >> 8))*128 + r)*NEP + e];
}

// ---- transpose W (needed cols only) into [k][e] with zero pad to WTS ----
__global__ void k_wt(const float* __restrict__ in_proj_w){
    int i = blockIdx.x*blockDim.x + threadIdx.x;
    if (i >= 192*WTS) return;
    int k = i / WTS, e = i % WTS;
    g_Wt[i] = (e < NEP) ? in_proj_w[(size_t)wrow_of(e)*DM + k] : 0.f;
}

// ---- positional encoding rows projected through W (shared by all batches) ----
__global__ void k_peproj(const float* __restrict__ in_proj_w){
    __shared__ float pe[DM];
    int t = blockIdx.x;
    int tid = threadIdx.x;
    if (tid < DM){
        float expo = -(float)(tid & ~1) * (logf(10000.0f)/(float)DM);
        float div = expf(expo);
        float ang = (float)t * div;
        pe[tid] = (tid & 1) ? cosf(ang) : sinf(ang);
    }
    __syncthreads();
    for (int e = tid; e < NEP; e += blockDim.x){
        const float* wr = in_proj_w + (size_t)wrow_of(e)*DM;
        float s = 0.f;
        for (int d = 0; d < DM; d++) s += pe[d]*wr[d];
        g_peproj[t*NEP + e] = s;
    }
}

// ---- const-pad conv+silu values per t, plus pad dt/logdA per (t,h) ----
__global__ void k_xc(const float* __restrict__ conv_w, const float* __restrict__ conv_b,
                     const float* __restrict__ dt_bias, const float* __restrict__ A_log){
    int t = blockIdx.x;
    int tid = threadIdx.x;
    for (int c = tid; c < 896; c += 256){
        float4 wv = *(const float4*)(conv_w + (size_t)c*4);
        float v = conv_b[c] + g_peproj[t*NEP + c]*(wv.x + wv.y + wv.z + wv.w);
        g_xc[t*896 + c] = silu_f(v);
    }
    if (tid < NH){
        float z = g_peproj[t*NEP + 896 + tid] + dt_bias[tid];
        float dt = softplus_f(z);
        g_dtpad[t*NH + tid] = dt;
        g_ldpad[t*NH + tid] = -expf(A_log[tid])*dt;
    }
}

// ---- main GEMM: 16384 real rows x 920(->1024) cols x K=192, + peproj bias ----
__global__ void __launch_bounds__(256, 2) k_gemm(const float* __restrict__ inputs){
    int bt = blockIdx.x;
    int t = bt & 7;
    int e0 = blockIdx.y * 128;
    const float* A = inputs + ((size_t)bt*129 + 1)*DM;
    __shared__ float As[2][16][128];
    __shared__ float Bs[2][16][128];
    int tid = threadIdx.x;
    int am = tid & 127, kq = (tid >> 7) * 8;
    int bk = tid >> 5,  bj = (tid & 31) * 4;
    int ty = tid >> 4,  tx = tid & 15;
    float acc[8][8];
    #pragma unroll
    for (int i = 0; i < 8; i++)
        #pragma unroll
        for (int j = 0; j < 8; j++) acc[i][j] = 0.f;

    float4 ra0, ra1, rb0, rb1;
    ra0 = *(const float4*)(A + (size_t)am*DM + kq);
    ra1 = *(const float4*)(A + (size_t)am*DM + kq + 4);
    rb0 = *(const float4*)(g_Wt + (size_t)bk*WTS + e0 + bj);
    rb1 = *(const float4*)(g_Wt + (size_t)(bk + 8)*WTS + e0 + bj);
    As[0][kq+0][am] = ra0.x; As[0][kq+1][am] = ra0.y; As[0][kq+2][am] = ra0.z; As[0][kq+3][am] = ra0.w;
    As[0][kq+4][am] = ra1.x; As[0][kq+5][am] = ra1.y; As[0][kq+6][am] = ra1.z; As[0][kq+7][am] = ra1.w;
    *(float4*)&Bs[0][bk][bj]     = rb0;
    *(float4*)&Bs[0][bk+8][bj]   = rb1;
    __syncthreads();

    #pragma unroll 1
    for (int kb = 0; kb < 12; kb++){
        int cur = kb & 1;
        if (kb < 11){
            int k0 = (kb + 1) * 16;
            ra0 = *(const float4*)(A + (size_t)am*DM + k0 + kq);
            ra1 = *(const float4*)(A + (size_t)am*DM + k0 + kq + 4);
            rb0 = *(const float4*)(g_Wt + (size_t)(k0 + bk)*WTS + e0 + bj);
            rb1 = *(const float4*)(g_Wt + (size_t)(k0 + bk + 8)*WTS + e0 + bj);
        }
        #pragma unroll
        for (int k = 0; k < 16; k++){
            float4 av0 = *(const float4*)&As[cur][k][ty*4];
            float4 av1 = *(const float4*)&As[cur][k][ty*4 + 64];
            float4 bv0 = *(const float4*)&Bs[cur][k][tx*4];
            float4 bv1 = *(const float4*)&Bs[cur][k][tx*4 + 64];
            float ar[8] = {av0.x, av0.y, av0.z, av0.w, av1.x, av1.y, av1.z, av1.w};
            float br[8] = {bv0.x, bv0.y, bv0.z, bv0.w, bv1.x, bv1.y, bv1.z, bv1.w};
            #pragma unroll
            for (int i = 0; i < 8; i++)
                #pragma unroll
                for (int j = 0; j < 8; j++)
                    acc[i][j] += ar[i]*br[j];
        }
        if (kb < 11){
            int nxt = cur ^ 1;
            As[nxt][kq+0][am] = ra0.x; As[nxt][kq+1][am] = ra0.y;
            As[nxt][kq+2][am] = ra0.z; As[nxt][kq+3][am] = ra0.w;
            As[nxt][kq+4][am] = ra1.x; As[nxt][kq+5][am] = ra1.y;
            As[nxt][kq+6][am] = ra1.z; As[nxt][kq+7][am] = ra1.w;
            *(float4*)&Bs[nxt][bk][bj]   = rb0;
            *(float4*)&Bs[nxt][bk+8][bj] = rb1;
            __syncthreads();
        }
    }

    float bias[8];
    #pragma unroll
    for (int j = 0; j < 8; j++){
        int e = e0 + tx*4 + (j >> 2)*64 + (j & 3);
        bias[j] = (e < NEP) ? g_peproj[t*NEP + e] : 0.f;
    }
    #pragma unroll
    for (int i = 0; i < 8; i++){
        int s = ty*4 + (i >> 2)*64 + (i & 3);
        float* dst = g_projR + ((size_t)bt*128 + s)*NEP;
        int eA = e0 + tx*4;
        if (eA < NEP){
            float4 v = make_float4(acc[i][0]+bias[0], acc[i][1]+bias[1],
                                   acc[i][2]+bias[2], acc[i][3]+bias[3]);
            *(float4*)(dst + eA) = v;
        }
        int eB = e0 + tx*4 + 64;
        if (eB < NEP){
            float4 v = make_float4(acc[i][4]+bias[4], acc[i][5]+bias[5],
                                   acc[i][6]+bias[6], acc[i][7]+bias[7]);
            *(float4*)(dst + eB) = v;
        }
    }
}

// ---- per-(b,h) scan: parallel within-chunk suffix scan, fp64 across chunks ----
// Writes w only where consumed: real rows s<128, pad s in [128,136); wsum closed-form.
__global__ void __launch_bounds__(128) k_scan(const float* __restrict__ dt_bias,
                                              const float* __restrict__ A_log){
    int b = blockIdx.x / NH, h = blockIdx.x % NH;
    int tid = threadIdx.x;
    float db = dt_bias[h];
    float nA = expf(A_log[h]);
    float dtv[8], ldv[8], v[8];
    #pragma unroll
    for (int t = 0; t < 8; t++){
        float z = g_projR[(((size_t)(b*8 + t))*128 + tid)*NEP + 896 + h] + db;
        float dt = softplus_f(z);
        dtv[t] = dt;
        ldv[t] = -nA*dt;
        v[t] = ldv[t];
    }
    __shared__ float sm[128][9];
    #pragma unroll
    for (int off = 1; off < 128; off <<= 1){
        __syncthreads();
        #pragma unroll
        for (int t = 0; t < 8; t++) sm[tid][t] = v[t];
        __syncthreads();
        if (tid + off < 128){
            #pragma unroll
            for (int t = 0; t < 8; t++) v[t] += sm[tid + off][t];
        }
    }
    float excl[8];
    #pragma unroll
    for (int t = 0; t < 8; t++) excl[t] = v[t] - ldv[t];
    __shared__ float totsh[8];
    if (tid == 0){
        #pragma unroll
        for (int t = 0; t < 8; t++) totsh[t] = v[t];
    }
    __syncthreads();
    float ldp[8], dtp[8];
    #pragma unroll
    for (int t = 0; t < 8; t++){ ldp[t] = g_ldpad[t*NH + h]; dtp[t] = g_dtpad[t*NH + h]; }
    double Gt[8];
    Gt[7] = 0.0;
    #pragma unroll
    for (int t = 6; t >= 0; t--)
        Gt[t] = Gt[t+1] + (double)totsh[t+1] + 128.0*(double)ldp[t+1];
    size_t wbase = (size_t)(b*NH + h)*LT;
    #pragma unroll
    for (int t = 0; t < 8; t++){
        float tail = excl[t] + 128.f*ldp[t] + (float)Gt[t];
        g_w[wbase + t*256 + tid] = dtv[t]*expf(tail);
        if (tid == 2) g_tail2[(b*NH + h)*NT + t] = tail;
    }
    if (tid < 8){
        int s = 128 + tid;
        #pragma unroll
        for (int t = 0; t < 8; t++)
            g_w[wbase + t*256 + s] = dtp[t]*expf((float)(255 - s)*ldp[t] + (float)Gt[t]);
    }
    if (tid < 8){
        int t = tid;
        double ld = (double)ldp[t];
        double geo = expm1(125.0*ld)/expm1(ld);
        g_wsum[(b*8 + t)*NH + h] = (float)((double)dtp[t]*exp(Gt[t])*geo);
    }
}

// ---- fused conv(4)+silu + head-combine, only positions s in [0,136) per chunk ----
__global__ void __launch_bounds__(256) k_convy(const float* __restrict__ conv_w,
                                               const float* __restrict__ conv_b){
    int bt = blockIdx.x / 17;
    int j17 = blockIdx.x - bt*17;
    int b = bt >> 3, t = bt & 7;
    int l0 = t*256 + j17*8;
    int tid = threadIdx.x;
    __shared__ float pt[11][896];
    __shared__ float wsm[8][NH];
    __shared__ float ypart[256][8];
    for (int i = tid; i < 11*896; i += 256){
        int r = i / 896, c = i - r*896;
        int gl = l0 - 3 + r;
        pt[r][c] = (gl >= 0) ? ld_proj(b, gl, c) : 0.f;
    }
    if (tid < 8*NH){
        int jl = tid >> 5;           // not used for mapping; direct decode:
        int l = tid / NH, h = tid - l*NH;
        wsm[l][h] = g_w[((size_t)(b*NH + h))*LT + l0 + l];
        (void)jl;
    }
    int c0 = tid, c1 = tid + 256, c2 = tid + 512;
    float4 w0 = *(const float4*)(conv_w + (size_t)c0*4);
    float4 w1 = *(const float4*)(conv_w + (size_t)c1*4);
    float4 w2 = *(const float4*)(conv_w + (size_t)c2*4);
    float cb0 = conv_b[c0], cb1 = conv_b[c1], cb2 = conv_b[c2];
    float4 wB = make_float4(0.f,0.f,0.f,0.f); float cbB = 0.f;
    if (tid < 128){ wB = *(const float4*)(conv_w + (size_t)(768 + tid)*4); cbB = conv_b[768 + tid]; }
    int h0 = tid >> 5;
    __syncthreads();
    float yl[8];
    #pragma unroll
    for (int j = 0; j < 8; j++){
        float v0 = cb0 + pt[j][c0]*w0.x + pt[j+1][c0]*w0.y + pt[j+2][c0]*w0.z + pt[j+3][c0]*w0.w;
        float v1 = cb1 + pt[j][c1]*w1.x + pt[j+1][c1]*w1.y + pt[j+2][c1]*w1.z + pt[j+3][c1]*w1.w;
        float v2 = cb2 + pt[j][c2]*w2.x + pt[j+1][c2]*w2.y + pt[j+2][c2]*w2.z + pt[j+3][c2]*w2.w;
        yl[j] = silu_f(v0)*wsm[j][h0] + silu_f(v1)*wsm[j][h0+8] + silu_f(v2)*wsm[j][h0+16];
        if (tid < 128){
            int cB = 768 + tid;
            float vB = cbB + pt[j][cB]*wB.x + pt[j+1][cB]*wB.y + pt[j+2][cB]*wB.z + pt[j+3][cB]*wB.w;
            g_B[((size_t)b*LT + l0 + j)*DS + tid] = silu_f(vB);
        }
    }
    #pragma unroll
    for (int j = 0; j < 8; j++) ypart[tid][j] = yl[j];
    __syncthreads();
    {
        int l = tid >> 5, p = tid & 31;
        float y = 0.f;
        #pragma unroll
        for (int g = 0; g < 8; g++) y += ypart[g*32 + p][l];
        g_y[((size_t)b*LT + l0 + l)*HD + p] = y;
    }
}

// ---- segment outer products over real+boundary range [256t+3, 256t+131), 2 subs of 64,
//      sub==1 also folds the next chunk's first 3 rows (C-range) ----
__global__ void __launch_bounds__(128) k_seg(){
    int idx = blockIdx.x;
    int b = idx >> 4, t = (idx >> 1) & 7, sub = idx & 1;
    int lbeg = t*256 + 3 + sub*64;
    int lend = lbeg + 64;
    int n = threadIdx.x;
    __shared__ float ysm[8][HD];
    float acc[HD];
    #pragma unroll
    for (int p = 0; p < HD; p++) acc[p] = 0.f;
    for (int l8 = lbeg; l8 < lend; l8 += 8){
        __syncthreads();
        for (int i = n; i < 8*HD; i += 128)
            ysm[i >> 5][i & 31] = g_y[((size_t)b*LT + l8 + (i >> 5))*HD + (i & 31)];
        __syncthreads();
        #pragma unroll
        for (int j = 0; j < 8; j++){
            float Bn = g_B[((size_t)b*LT + l8 + j)*DS + n];
            #pragma unroll
            for (int p = 0; p < HD; p++) acc[p] += ysm[j][p]*Bn;
        }
    }
    if (sub == 1 && t < 7){
        int lc = (t + 1)*256;
        __syncthreads();
        for (int i = n; i < 3*HD; i += 128)
            ysm[i >> 5][i & 31] = g_y[((size_t)b*LT + lc + (i >> 5))*HD + (i & 31)];
        __syncthreads();
        #pragma unroll
        for (int j = 0; j < 3; j++){
            float Bn = g_B[((size_t)b*LT + lc + j)*DS + n];
            #pragma unroll
            for (int p = 0; p < HD; p++) acc[p] += ysm[j][p]*Bn;
        }
    }
    float* Z = g_Zsub + (size_t)idx*4096;
    #pragma unroll
    for (int p = 0; p < HD; p++) Z[p*DS + n] = acc[p];
}

// ---- per-(b,t) 3-position boundary correction (truncated conv of each suffix) ----
__global__ void __launch_bounds__(128) k_bdry(const float* __restrict__ conv_w,
                                              const float* __restrict__ conv_b,
                                              const float* __restrict__ dt_bias,
                                              const float* __restrict__ A_log){
    int b = blockIdx.x >> 3, t = blockIdx.x & 7;
    int tid = threadIdx.x;
    __shared__ float xsb[3][896];
    __shared__ float dtb[3][NH], ldb[3][NH], wjs[3][NH];
    __shared__ float ysh[3][HD];
    for (int c = tid; c < 896; c += 128){
        float4 wv = *(const float4*)(conv_w + (size_t)c*4);
        float w[4] = {wv.x, wv.y, wv.z, wv.w};
        float cb = conv_b[c];
        #pragma unroll
        for (int j = 0; j < 3; j++){
            float v = cb;
            for (int k = 3-j; k <= 3; k++)
                v += g_projR[(((size_t)(b*NT + t))*128 + (j - 3 + k))*NEP + c]*w[k];
            xsb[j][c] = silu_f(v);
        }
    }
    if (tid < NH){
        int h = tid;
        float db = dt_bias[h], nA = expf(A_log[h]);
        for (int j = 0; j < 3; j++){
            float z = g_projR[(((size_t)(b*NT + t))*128 + j)*NEP + 896 + h] + db;
            float dt = softplus_f(z);
            dtb[j][h] = dt; ldb[j][h] = -nA*dt;
        }
    }
    __syncthreads();
    if (tid < NH){
        int h = tid;
        float t2 = g_tail2[(b*NH + h)*NT + t];
        wjs[2][h] = dtb[2][h]*expf(t2);
        float t1 = t2 + ldb[2][h];
        wjs[1][h] = dtb[1][h]*expf(t1);
        float t0 = t1 + ldb[1][h];
        wjs[0][h] = dtb[0][h]*expf(t0);
    }
    __syncthreads();
    if (tid < 96){
        int j = tid >> 5, p = tid & 31;
        float y = 0.f;
        #pragma unroll
        for (int h = 0; h < NH; h++) y += wjs[j][h]*xsb[j][h*HD + p];
        ysh[j][p] = y;
    }
    __syncthreads();
    int n = tid;
    float B0 = xsb[0][768+n], B1 = xsb[1][768+n], B2 = xsb[2][768+n];
    float* C = g_C + (size_t)blockIdx.x*4096;
    #pragma unroll
    for (int p = 0; p < HD; p++)
        C[p*DS + n] = ysh[0][p]*B0 + ysh[1][p]*B1 + ysh[2][p]*B2;
}

// ---- suffix-sum segments + rank-1 pad term + boundary corrections ----
__global__ void __launch_bounds__(256) k_finalS(){
    int b = blockIdx.x;
    int tid = threadIdx.x;
    __shared__ float ysh[8][32];
    {
        int t = tid >> 5, p = tid & 31;
        float s = 0.f;
        #pragma unroll
        for (int h = 0; h < NH; h++)
            s += g_wsum[(b*8 + t)*NH + h]*g_xc[t*896 + h*HD + p];
        ysh[t][p] = s;
    }
    __syncthreads();
    int i = blockIdx.y*256 + tid;
    int p = i >> 7, n = i & 127;
    float run = 0.f;
    for (int t = 7; t >= 0; t--){
        size_t zb = ((size_t)(b*8 + t))*2*4096 + i;
        run += g_Zsub[zb] + g_Zsub[zb + 4096] + ysh[t][p]*g_xc[t*896 + 768 + n];
        g_S[(size_t)(b*8 + t)*4096 + i] = run + g_C[(size_t)(b*8 + t)*4096 + i];
    }
}

// ---- classifier GEMM, split-K into deterministic partials ----
__global__ void __launch_bounds__(256) k_cls(const float* __restrict__ cls_w){
    int m0 = blockIdx.x*32, n0 = blockIdx.y*32;
    int kz0 = blockIdx.z*512;
    __shared__ float As[32][33], Bs[32][33];
    int tid = threadIdx.x;
    int tx = tid & 15, ty = tid >> 4;
    int am = tid >> 3, aq = (tid & 7)*4;
    float acc00 = 0, acc01 = 0, acc10 = 0, acc11 = 0;
    bool bvalid = (n0 + am) < 100;
    for (int k0 = kz0; k0 < kz0 + 512; k0 += 32){
        float4 av = *reinterpret_cast<const float4*>(g_S + (size_t)(m0 + am)*4096 + k0 + aq);
        float4 bv = bvalid ? *reinterpret_cast<const float4*>(cls_w + (size_t)(n0 + am)*4096 + k0 + aq)
                           : make_float4(0.f, 0.f, 0.f, 0.f);
        __syncthreads();
        As[am][aq+0] = av.x; As[am][aq+1] = av.y; As[am][aq+2] = av.z; As[am][aq+3] = av.w;
        Bs[aq+0][am] = bv.x; Bs[aq+1][am] = bv.y; Bs[aq+2][am] = bv.z; Bs[aq+3][am] = bv.w;
        __syncthreads();
        #pragma unroll
        for (int k = 0; k < 32; k++){
            float a0 = As[ty*2][k],   a1 = As[ty*2+1][k];
            float b0 = Bs[k][tx*2],   b1 = Bs[k][tx*2+1];
            acc00 += a0*b0; acc01 += a0*b1; acc10 += a1*b0; acc11 += a1*b1;
        }
    }
    int m = m0 + ty*2, n = n0 + tx*2;
    float* P = g_part + (size_t)blockIdx.z*12800;
    if (n < 100)    { P[m*100 + n]     = acc00; P[(m+1)*100 + n]     = acc10; }
    if (n + 1 < 100){ P[m*100 + n + 1] = acc01; P[(m+1)*100 + n + 1] = acc11; }
}

__global__ void k_out(const float* __restrict__ cls_b, float* __restrict__ out){
    int i = blockIdx.x*blockDim.x + threadIdx.x;
    if (i >= 12800) return;
    int k = i % 100;
    float s = cls_b[k];
    #pragma unroll
    for (int z = 0; z < 8; z++) s += g_part[z*12800 + i];
    out[i] = s;
}

extern "C" void kernel_launch(void* const* d_in, const int* in_sizes, int n_in,
                              void* d_out, int out_size){
    const float* inputs    = (const float*)d_in[0];
    const float* in_proj_w = (const float*)d_in[1];
    const float* conv_w    = (const float*)d_in[2];
    const float* conv_b    = (const float*)d_in[3];
    const float* dt_bias   = (const float*)d_in[4];
    const float* A_log     = (const float*)d_in[5];
    const float* cls_w     = (const float*)d_in[6];
    const float* cls_b     = (const float*)d_in[7];
    float* out = (float*)d_out;

    k_wt<<<768, 256>>>(in_proj_w);
    k_peproj<<<8, 256>>>(in_proj_w);
    k_xc<<<8, 256>>>(conv_w, conv_b, dt_bias, A_log);
    k_gemm<<<dim3(128, 8), 256>>>(inputs);
    k_scan<<<16*24, 128>>>(dt_bias, A_log);
    k_convy<<<16*8*17, 256>>>(conv_w, conv_b);
    k_seg<<<256, 128>>>();
    k_bdry<<<128, 128>>>(conv_w, conv_b, dt_bias, A_log);
    k_finalS<<<dim3(16, 16), 256>>>();
    k_cls<<<dim3(4, 4, 8), 256>>>(cls_w);
    k_out<<<50, 256>>>(cls_b, out);
}

// round 7
// speedup vs baseline: 1.6495x; 1.0507x over previous
#include <cuda_runtime.h>
#include <cuda_bf16.h>
#include <math.h>

#define NB 16
#define NT 8
#define LT 2048
#define NEP 920
#define NH 24
#define HD 32
#define DS 128
#define DM 192
#define KV 576      // virtual K for bf16x3

__device__ float g_projR[(size_t)NB*NT*128*NEP];
__device__ float g_y[(size_t)NB*LT*HD];
__device__ float g_B[(size_t)NB*LT*DS];
__device__ float g_w[(size_t)NB*NH*LT];          // [b][h][l]
__device__ float g_tail2[NB*NH*NT];
__device__ float g_wsum[NB*NT*NH];
__device__ float g_Zsub[NB*8*2*4096];
__device__ float g_C[NB*8*4096];
__device__ float g_S[NB*8*4096];
__device__ float g_part[8*128*100];
__device__ float g_peproj[8*NEP];
__device__ float g_xc[8*896];
__device__ float g_dtpad[8*NH];
__device__ float g_ldpad[8*NH];
__device__ __nv_bfloat16 g_Bcat[1024*KV];        // [e][kv], kv = [hi | lo | hi]

__device__ __forceinline__ float softplus_f(float z){
    return log1pf(expf(-fabsf(z))) + fmaxf(z, 0.f);
}
__device__ __forceinline__ float silu_f(float v){
    return v / (1.f + expf(-v));
}
__device__ __forceinline__ int wrow_of(int ce){
    return (ce < 896) ? (768 + ce) : (896 + ce);
}
__device__ __forceinline__ float ld_proj(int b, int l, int e){
    int r = l & 255;
    if (r >= 128) return g_peproj[(l >> 8)*NEP + e];
    return g_projR[(((size_t)b*NT + (l >> 8))*128 + r)*NEP + e];
}

// ---- positional encoding rows projected through W ----
__global__ void k_peproj(const float* __restrict__ in_proj_w){
    __shared__ float pe[DM];
    int t = blockIdx.x;
    int tid = threadIdx.x;
    if (tid < DM){
        float expo = -(float)(tid & ~1) * (logf(10000.0f)/(float)DM);
        float div = expf(expo);
        float ang = (float)t * div;
        pe[tid] = (tid & 1) ? cosf(ang) : sinf(ang);
    }
    __syncthreads();
    for (int e = tid; e < NEP; e += blockDim.x){
        const float* wr = in_proj_w + (size_t)wrow_of(e)*DM;
        float s = 0.f;
        for (int d = 0; d < DM; d++) s += pe[d]*wr[d];
        g_peproj[t*NEP + e] = s;
    }
}

// ---- const-pad conv+silu per t, pad dt/logdA per (t,h) ----
__global__ void k_xc(const float* __restrict__ conv_w, const float* __restrict__ conv_b,
                     const float* __restrict__ dt_bias, const float* __restrict__ A_log){
    int t = blockIdx.x;
    int tid = threadIdx.x;
    for (int c = tid; c < 896; c += 256){
        float4 wv = *(const float4*)(conv_w + (size_t)c*4);
        float v = conv_b[c] + g_peproj[t*NEP + c]*(wv.x + wv.y + wv.z + wv.w);
        g_xc[t*896 + c] = silu_f(v);
    }
    if (tid < NH){
        float z = g_peproj[t*NEP + 896 + tid] + dt_bias[tid];
        float dt = softplus_f(z);
        g_dtpad[t*NH + tid] = dt;
        g_ldpad[t*NH + tid] = -expf(A_log[tid])*dt;
    }
}

// ---- pack weight matrix into bf16x3 catalog [e][hi|lo|hi] ----
__global__ void k_bprep(const float* __restrict__ in_proj_w){
    int e = blockIdx.x, k = threadIdx.x;
    __nv_bfloat16 hi, lo;
    if (e < NEP){
        float w = in_proj_w[(size_t)wrow_of(e)*DM + k];
        hi = __float2bfloat16(w);
        lo = __float2bfloat16(w - __bfloat162float(hi));
    } else {
        hi = __float2bfloat16(0.f); lo = hi;
    }
    g_Bcat[(size_t)e*KV + k]        = hi;
    g_Bcat[(size_t)e*KV + 192 + k]  = lo;
    g_Bcat[(size_t)e*KV + 384 + k]  = hi;
}

// ---- main GEMM on tensor pipe: bf16x3 mma.sync, 128x128 tile ----
__global__ void __launch_bounds__(256) k_gemm(const float* __restrict__ inputs){
    int bt = blockIdx.x;
    int t = bt & 7;
    int n0 = blockIdx.y * 128;
    const float* A = inputs + ((size_t)bt*129 + 1)*DM;
    __shared__ __nv_bfloat16 As[2][128][24];
    __shared__ __nv_bfloat16 Bs[2][128][24];
    int tid = threadIdx.x;
    int srow = tid >> 1, half = tid & 1;           // staging: row, 8-elem half
    int wid = tid >> 5, lane = tid & 31;
    int wm = (wid & 1)*64, wn = (wid >> 1)*32;
    int gid = lane >> 2, tig = lane & 3;

    float acc[4][4][4];
    #pragma unroll
    for (int i = 0; i < 4; i++)
        #pragma unroll
        for (int j = 0; j < 4; j++)
            #pragma unroll
            for (int q = 0; q < 4; q++) acc[i][j][q] = 0.f;

    // stage step s into buffer buf
    auto stage = [&](int s, int buf){
        // A: fp32 group s%12, convert hi (s<24) or lo (s>=24)
        int grp = s % 12;
        bool lo = (s >= 24);
        const float* src = A + (size_t)srow*DM + grp*16 + half*8;
        float4 v0 = *(const float4*)src;
        float4 v1 = *(const float4*)(src + 4);
        float f[8] = {v0.x, v0.y, v0.z, v0.w, v1.x, v1.y, v1.z, v1.w};
        __nv_bfloat16 hb[8];
        #pragma unroll
        for (int i = 0; i < 8; i++){
            __nv_bfloat16 hi = __float2bfloat16(f[i]);
            hb[i] = lo ? __float2bfloat16(f[i] - __bfloat162float(hi)) : hi;
        }
        *(uint4*)&As[buf][srow][half*8] = *(uint4*)hb;
        // B: direct bf16 copy
        uint4 bv = *(const uint4*)(g_Bcat + (size_t)(n0 + srow)*KV + s*16 + half*8);
        *(uint4*)&Bs[buf][srow][half*8] = bv;
    };

    stage(0, 0);
    __syncthreads();

    #pragma unroll 1
    for (int s = 0; s < 36; s++){
        int cur = s & 1;
        if (s < 35) stage(s + 1, cur ^ 1);
        unsigned aF[4][4], bF[4][2];
        #pragma unroll
        for (int mt = 0; mt < 4; mt++){
            int r = wm + mt*16 + gid;
            aF[mt][0] = *(const unsigned*)&As[cur][r][tig*2];
            aF[mt][1] = *(const unsigned*)&As[cur][r+8][tig*2];
            aF[mt][2] = *(const unsigned*)&As[cur][r][tig*2+8];
            aF[mt][3] = *(const unsigned*)&As[cur][r+8][tig*2+8];
        }
        #pragma unroll
        for (int nt = 0; nt < 4; nt++){
            int n = wn + nt*8 + gid;
            bF[nt][0] = *(const unsigned*)&Bs[cur][n][tig*2];
            bF[nt][1] = *(const unsigned*)&Bs[cur][n][tig*2+8];
        }
        #pragma unroll
        for (int mt = 0; mt < 4; mt++)
            #pragma unroll
            for (int nt = 0; nt < 4; nt++){
                asm volatile(
                    "mma.sync.aligned.m16n8k16.row.col.f32.bf16.bf16.f32 "
                    "{%0,%1,%2,%3}, {%4,%5,%6,%7}, {%8,%9}, {%0,%1,%2,%3};"
                    : "+f"(acc[mt][nt][0]), "+f"(acc[mt][nt][1]),
                      "+f"(acc[mt][nt][2]), "+f"(acc[mt][nt][3])
                    : "r"(aF[mt][0]), "r"(aF[mt][1]), "r"(aF[mt][2]), "r"(aF[mt][3]),
                      "r"(bF[nt][0]), "r"(bF[nt][1]));
            }
        if (s < 35) __syncthreads();
    }

    // epilogue: + PE bias, store real rows (e < 920)
    #pragma unroll
    for (int mt = 0; mt < 4; mt++){
        #pragma unroll
        for (int nt = 0; nt < 4; nt++){
            int e = n0 + wn + nt*8 + tig*2;
            if (e >= NEP) continue;
            float b0 = g_peproj[t*NEP + e];
            float b1 = g_peproj[t*NEP + e + 1];
            int r0 = wm + mt*16 + gid;
            float* d0 = g_projR + ((size_t)bt*128 + r0)*NEP + e;
            float* d1 = g_projR + ((size_t)bt*128 + r0 + 8)*NEP + e;
            float2 v0 = make_float2(acc[mt][nt][0] + b0, acc[mt][nt][1] + b1);
            float2 v1 = make_float2(acc[mt][nt][2] + b0, acc[mt][nt][3] + b1);
            *(float2*)d0 = v0;
            *(float2*)d1 = v1;
        }
    }
}

// ---- per-(b,h) scan: parallel within-chunk suffix scan, fp64 across chunks ----
__global__ void __launch_bounds__(128) k_scan(const float* __restrict__ dt_bias,
                                              const float* __restrict__ A_log){
    int b = blockIdx.x / NH, h = blockIdx.x % NH;
    int tid = threadIdx.x;
    float db = dt_bias[h];
    float nA = expf(A_log[h]);
    float dtv[8], ldv[8], v[8];
    #pragma unroll
    for (int t = 0; t < 8; t++){
        float z = g_projR[(((size_t)(b*8 + t))*128 + tid)*NEP + 896 + h] + db;
        float dt = softplus_f(z);
        dtv[t] = dt;
        ldv[t] = -nA*dt;
        v[t] = ldv[t];
    }
    __shared__ float sm[128][9];
    #pragma unroll
    for (int off = 1; off < 128; off <<= 1){
        __syncthreads();
        #pragma unroll
        for (int t = 0; t < 8; t++) sm[tid][t] = v[t];
        __syncthreads();
        if (tid + off < 128){
            #pragma unroll
            for (int t = 0; t < 8; t++) v[t] += sm[tid + off][t];
        }
    }
    float excl[8];
    #pragma unroll
    for (int t = 0; t < 8; t++) excl[t] = v[t] - ldv[t];
    __shared__ float totsh[8];
    if (tid == 0){
        #pragma unroll
        for (int t = 0; t < 8; t++) totsh[t] = v[t];
    }
    __syncthreads();
    float ldp[8], dtp[8];
    #pragma unroll
    for (int t = 0; t < 8; t++){ ldp[t] = g_ldpad[t*NH + h]; dtp[t] = g_dtpad[t*NH + h]; }
    double Gt[8];
    Gt[7] = 0.0;
    #pragma unroll
    for (int t = 6; t >= 0; t--)
        Gt[t] = Gt[t+1] + (double)totsh[t+1] + 128.0*(double)ldp[t+1];
    size_t wbase = (size_t)(b*NH + h)*LT;
    #pragma unroll
    for (int t = 0; t < 8; t++){
        float tail = excl[t] + 128.f*ldp[t] + (float)Gt[t];
        g_w[wbase + t*256 + tid] = dtv[t]*expf(tail);
        if (tid == 2) g_tail2[(b*NH + h)*NT + t] = tail;
    }
    if (tid < 16){
        int s = 128 + tid;
        #pragma unroll
        for (int t = 0; t < 8; t++)
            g_w[wbase + t*256 + s] = dtp[t]*expf((float)(255 - s)*ldp[t] + (float)Gt[t]);
    }
    if (tid < 8){
        int t = tid;
        double ld = (double)ldp[t];
        double geo = expm1(125.0*ld)/expm1(ld);
        g_wsum[(b*8 + t)*NH + h] = (float)((double)dtp[t]*exp(Gt[t])*geo);
    }
}

// ---- fused conv(4)+silu + head-combine, register rolling windows, 16 l per block ----
__global__ void __launch_bounds__(256) k_convy(const float* __restrict__ conv_w,
                                               const float* __restrict__ conv_b){
    int blk = blockIdx.x;
    int bt = blk / 9, j9 = blk - bt*9;
    int b = bt >> 3, t = bt & 7;
    int l0 = t*256 + j9*16;
    int tid = threadIdx.x;
    __shared__ float wsm[16][NH];
    __shared__ float ypart[256][17];
    for (int i = tid; i < 16*NH; i += 256){
        int l = i / NH, h = i - l*NH;
        wsm[l][h] = g_w[((size_t)(b*NH + h))*LT + l0 + l];
    }
    int c0 = tid, c1 = tid + 256, c2 = tid + 512, cB = 768 + (tid & 127);
    float4 w0 = *(const float4*)(conv_w + (size_t)c0*4);
    float4 w1 = *(const float4*)(conv_w + (size_t)c1*4);
    float4 w2 = *(const float4*)(conv_w + (size_t)c2*4);
    float cb0 = conv_b[c0], cb1 = conv_b[c1], cb2 = conv_b[c2];
    float4 wB = make_float4(0.f,0.f,0.f,0.f); float cbB = 0.f;
    bool doB = (tid < 128);
    if (doB){ wB = *(const float4*)(conv_w + (size_t)cB*4); cbB = conv_b[cB]; }
    int h0 = tid >> 5;
    float u0[4], u1[4], u2[4], uB[4];
    #pragma unroll
    for (int k = 1; k < 4; k++){
        int gl = l0 - 4 + k;
        bool ok = (gl >= 0);
        u0[k] = ok ? ld_proj(b, gl, c0) : 0.f;
        u1[k] = ok ? ld_proj(b, gl, c1) : 0.f;
        u2[k] = ok ? ld_proj(b, gl, c2) : 0.f;
        uB[k] = (ok && doB) ? ld_proj(b, gl, cB) : 0.f;
    }
    __syncthreads();
    float yl[16];
    #pragma unroll
    for (int j = 0; j < 16; j++){
        int gl = l0 + j;
        u0[0]=u0[1]; u0[1]=u0[2]; u0[2]=u0[3]; u0[3]=ld_proj(b, gl, c0);
        u1[0]=u1[1]; u1[1]=u1[2]; u1[2]=u1[3]; u1[3]=ld_proj(b, gl, c1);
        u2[0]=u2[1]; u2[1]=u2[2]; u2[2]=u2[3]; u2[3]=ld_proj(b, gl, c2);
        uB[0]=uB[1]; uB[1]=uB[2]; uB[2]=uB[3]; uB[3]=doB ? ld_proj(b, gl, cB) : 0.f;
        float v0 = cb0 + u0[0]*w0.x + u0[1]*w0.y + u0[2]*w0.z + u0[3]*w0.w;
        float v1 = cb1 + u1[0]*w1.x + u1[1]*w1.y + u1[2]*w1.z + u1[3]*w1.w;
        float v2 = cb2 + u2[0]*w2.x + u2[1]*w2.y + u2[2]*w2.z + u2[3]*w2.w;
        yl[j] = silu_f(v0)*wsm[j][h0] + silu_f(v1)*wsm[j][h0+8] + silu_f(v2)*wsm[j][h0+16];
        if (doB){
            float vB = cbB + uB[0]*wB.x + uB[1]*wB.y + uB[2]*wB.z + uB[3]*wB.w;
            g_B[((size_t)b*LT + gl)*DS + (tid & 127)] = silu_f(vB);
        }
    }
    #pragma unroll
    for (int j = 0; j < 16; j++) ypart[tid][j] = yl[j];
    __syncthreads();
    #pragma unroll
    for (int half = 0; half < 2; half++){
        int l = half*8 + (tid >> 5), p = tid & 31;
        float y = 0.f;
        #pragma unroll
        for (int g = 0; g < 8; g++) y += ypart[g*32 + p][l];
        g_y[((size_t)b*LT + l0 + l)*HD + p] = y;
    }
}

// ---- segment outer products over [256t+3, 256t+131), 2 subs of 64 ----
__global__ void __launch_bounds__(128) k_seg(){
    int idx = blockIdx.x;
    int b = idx >> 4, t = (idx >> 1) & 7, sub = idx & 1;
    int lbeg = t*256 + 3 + sub*64;
    int lend = lbeg + 64;
    int n = threadIdx.x;
    __shared__ float ysm[8][HD];
    float acc[HD];
    #pragma unroll
    for (int p = 0; p < HD; p++) acc[p] = 0.f;
    for (int l8 = lbeg; l8 < lend; l8 += 8){
        __syncthreads();
        for (int i = n; i < 8*HD; i += 128)
            ysm[i >> 5][i & 31] = g_y[((size_t)b*LT + l8 + (i >> 5))*HD + (i & 31)];
        __syncthreads();
        #pragma unroll
        for (int j = 0; j < 8; j++){
            float Bn = g_B[((size_t)b*LT + l8 + j)*DS + n];
            #pragma unroll
            for (int p = 0; p < HD; p++) acc[p] += ysm[j][p]*Bn;
        }
    }
    if (sub == 1 && t < 7){
        int lc = (t + 1)*256;
        __syncthreads();
        for (int i = n; i < 3*HD; i += 128)
            ysm[i >> 5][i & 31] = g_y[((size_t)b*LT + lc + (i >> 5))*HD + (i & 31)];
        __syncthreads();
        #pragma unroll
        for (int j = 0; j < 3; j++){
            float Bn = g_B[((size_t)b*LT + lc + j)*DS + n];
            #pragma unroll
            for (int p = 0; p < HD; p++) acc[p] += ysm[j][p]*Bn;
        }
    }
    float* Z = g_Zsub + (size_t)idx*4096;
    #pragma unroll
    for (int p = 0; p < HD; p++) Z[p*DS + n] = acc[p];
}

// ---- per-(b,t) 3-position boundary correction ----
__global__ void __launch_bounds__(128) k_bdry(const float* __restrict__ conv_w,
                                              const float* __restrict__ conv_b,
                                              const float* __restrict__ dt_bias,
                                              const float* __restrict__ A_log){
    int b = blockIdx.x >> 3, t = blockIdx.x & 7;
    int tid = threadIdx.x;
    __shared__ float xsb[3][896];
    __shared__ float dtb[3][NH], ldb[3][NH], wjs[3][NH];
    __shared__ float ysh[3][HD];
    for (int c = tid; c < 896; c += 128){
        float4 wv = *(const float4*)(conv_w + (size_t)c*4);
        float w[4] = {wv.x, wv.y, wv.z, wv.w};
        float cb = conv_b[c];
        #pragma unroll
        for (int j = 0; j < 3; j++){
            float v = cb;
            for (int k = 3-j; k <= 3; k++)
                v += g_projR[(((size_t)(b*NT + t))*128 + (j - 3 + k))*NEP + c]*w[k];
            xsb[j][c] = silu_f(v);
        }
    }
    if (tid < NH){
        int h = tid;
        float db = dt_bias[h], nA = expf(A_log[h]);
        for (int j = 0; j < 3; j++){
            float z = g_projR[(((size_t)(b*NT + t))*128 + j)*NEP + 896 + h] + db;
            float dt = softplus_f(z);
            dtb[j][h] = dt; ldb[j][h] = -nA*dt;
        }
    }
    __syncthreads();
    if (tid < NH){
        int h = tid;
        float t2 = g_tail2[(b*NH + h)*NT + t];
        wjs[2][h] = dtb[2][h]*expf(t2);
        float t1 = t2 + ldb[2][h];
        wjs[1][h] = dtb[1][h]*expf(t1);
        float t0 = t1 + ldb[1][h];
        wjs[0][h] = dtb[0][h]*expf(t0);
    }
    __syncthreads();
    if (tid < 96){
        int j = tid >> 5, p = tid & 31;
        float y = 0.f;
        #pragma unroll
        for (int h = 0; h < NH; h++) y += wjs[j][h]*xsb[j][h*HD + p];
        ysh[j][p] = y;
    }
    __syncthreads();
    int n = tid;
    float B0 = xsb[0][768+n], B1 = xsb[1][768+n], B2 = xsb[2][768+n];
    float* C = g_C + (size_t)blockIdx.x*4096;
    #pragma unroll
    for (int p = 0; p < HD; p++)
        C[p*DS + n] = ysh[0][p]*B0 + ysh[1][p]*B1 + ysh[2][p]*B2;
}

// ---- suffix-sum segments + rank-1 pad term + boundary corrections ----
__global__ void __launch_bounds__(256) k_finalS(){
    int b = blockIdx.x;
    int tid = threadIdx.x;
    __shared__ float ysh[8][32];
    {
        int t = tid >> 5, p = tid & 31;
        float s = 0.f;
        #pragma unroll
        for (int h = 0; h < NH; h++)
            s += g_wsum[(b*8 + t)*NH + h]*g_xc[t*896 + h*HD + p];
        ysh[t][p] = s;
    }
    __syncthreads();
    int i = blockIdx.y*256 + tid;
    int p = i >> 7, n = i & 127;
    float run = 0.f;
    for (int t = 7; t >= 0; t--){
        size_t zb = ((size_t)(b*8 + t))*2*4096 + i;
        run += g_Zsub[zb] + g_Zsub[zb + 4096] + ysh[t][p]*g_xc[t*896 + 768 + n];
        g_S[(size_t)(b*8 + t)*4096 + i] = run + g_C[(size_t)(b*8 + t)*4096 + i];
    }
}

// ---- classifier GEMM, split-K ----
__global__ void __launch_bounds__(256) k_cls(const float* __restrict__ cls_w){
    int m0 = blockIdx.x*32, n0 = blockIdx.y*32;
    int kz0 = blockIdx.z*512;
    __shared__ float As[32][33], Bs[32][33];
    int tid = threadIdx.x;
    int tx = tid & 15, ty = tid >> 4;
    int am = tid >> 3, aq = (tid & 7)*4;
    float acc00 = 0, acc01 = 0, acc10 = 0, acc11 = 0;
    bool bvalid = (n0 + am) < 100;
    for (int k0 = kz0; k0 < kz0 + 512; k0 += 32){
        float4 av = *reinterpret_cast<const float4*>(g_S + (size_t)(m0 + am)*4096 + k0 + aq);
        float4 bv = bvalid ? *reinterpret_cast<const float4*>(cls_w + (size_t)(n0 + am)*4096 + k0 + aq)
                           : make_float4(0.f, 0.f, 0.f, 0.f);
        __syncthreads();
        As[am][aq+0] = av.x; As[am][aq+1] = av.y; As[am][aq+2] = av.z; As[am][aq+3] = av.w;
        Bs[aq+0][am] = bv.x; Bs[aq+1][am] = bv.y; Bs[aq+2][am] = bv.z; Bs[aq+3][am] = bv.w;
        __syncthreads();
        #pragma unroll
        for (int k = 0; k < 32; k++){
            float a0 = As[ty*2][k],   a1 = As[ty*2+1][k];
            float b0 = Bs[k][tx*2],   b1 = Bs[k][tx*2+1];
            acc00 += a0*b0; acc01 += a0*b1; acc10 += a1*b0; acc11 += a1*b1;
        }
    }
    int m = m0 + ty*2, n = n0 + tx*2;
    float* P = g_part + (size_t)blockIdx.z*12800;
    if (n < 100)    { P[m*100 + n]     = acc00; P[(m+1)*100 + n]     = acc10; }
    if (n + 1 < 100){ P[m*100 + n + 1] = acc01; P[(m+1)*100 + n + 1] = acc11; }
}

__global__ void k_out(const float* __restrict__ cls_b, float* __restrict__ out){
    int i = blockIdx.x*blockDim.x + threadIdx.x;
    if (i >= 12800) return;
    int k = i % 100;
    float s = cls_b[k];
    #pragma unroll
    for (int z = 0; z < 8; z++) s += g_part[z*12800 + i];
    out[i] = s;
}

extern "C" void kernel_launch(void* const* d_in, const int* in_sizes, int n_in,
                              void* d_out, int out_size){
    const float* inputs    = (const float*)d_in[0];
    const float* in_proj_w = (const float*)d_in[1];
    const float* conv_w    = (const float*)d_in[2];
    const float* conv_b    = (const float*)d_in[3];
    const float* dt_bias   = (const float*)d_in[4];
    const float* A_log     = (const float*)d_in[5];
    const float* cls_w     = (const float*)d_in[6];
    const float* cls_b     = (const float*)d_in[7];
    float* out = (float*)d_out;

    k_peproj<<<8, 256>>>(in_proj_w);
    k_xc<<<8, 256>>>(conv_w, conv_b, dt_bias, A_log);
    k_bprep<<<1024, 192>>>(in_proj_w);
    k_gemm<<<dim3(128, 8), 256>>>(inputs);
    k_scan<<<16*24, 128>>>(dt_bias, A_log);
    k_convy<<<128*9, 256>>>(conv_w, conv_b);
    k_seg<<<256, 128>>>();
    k_bdry<<<128, 128>>>(conv_w, conv_b, dt_bias, A_log);
    k_finalS<<<dim3(16, 16), 256>>>();
    k_cls<<<dim3(4, 4, 8), 256>>>(cls_w);
    k_out<<<50, 256>>>(cls_b, out);
}